// round 1
// baseline (speedup 1.0000x reference)
#include <cuda_runtime.h>
#include <cstdint>

// ---------------------------------------------------------------------------
// GCN-VAE encoder, fp32 SIMT baseline.
//   per layer: agg[i] = dinv_i * sum_{j in N(i) U {i}} dinv_j * t_j
//              out    = act(agg @ W + b)
// Aggregate-first ordering (aggregation commutes with the GEMM) so layer 1
// scatters 64 dims and mu/logvar share a single 128-dim aggregation.
// ---------------------------------------------------------------------------

#define N_NODES 100000
#define MAXD 128

__device__ float g_deg [N_NODES];
__device__ float g_dinv[N_NODES];
__device__ float g_bufA[(size_t)N_NODES * MAXD];   // aggregation accumulator
__device__ float g_bufB[(size_t)N_NODES * MAXD];   // hidden activations

// ----------------------------- degree / dinv -------------------------------

__global__ void k_init_deg(float* __restrict__ deg, int n) {
    int i = blockIdx.x * blockDim.x + threadIdx.x;
    if (i < n) deg[i] = 1.0f;   // self loop
}

__global__ void k_count_deg(const int* __restrict__ dst, float* __restrict__ deg, int E) {
    int i = blockIdx.x * blockDim.x + threadIdx.x;
    if (i < E) atomicAdd(&deg[dst[i]], 1.0f);
}

__global__ void k_dinv(const float* __restrict__ deg, float* __restrict__ dinv, int n) {
    int i = blockIdx.x * blockDim.x + threadIdx.x;
    if (i < n) dinv[i] = rsqrtf(deg[i]);
}

// --------------------------- aggregation kernels ---------------------------

// acc[i] = t[i] * dinv[i]   (self-loop contribution; initializes acc)
template <int D>
__global__ void k_init_acc(float* __restrict__ acc, const float* __restrict__ t,
                           const float* __restrict__ dinv, int n) {
    const int CH = D / 4;
    int i = blockIdx.x * blockDim.x + threadIdx.x;
    if (i >= n * CH) return;
    int row = i / CH;
    float4 v = reinterpret_cast<const float4*>(t)[i];
    float s = dinv[row];
    v.x *= s; v.y *= s; v.z *= s; v.w *= s;
    reinterpret_cast<float4*>(acc)[i] = v;
}

// acc[dst[e]] += t[src[e]] * dinv[src[e]]   (vector red.global.add.v4.f32)
template <int D>
__global__ void k_scatter(float* __restrict__ acc, const float* __restrict__ t,
                          const int* __restrict__ src, const int* __restrict__ dst,
                          const float* __restrict__ dinv, int E) {
    const int CH = D / 4;
    int i = blockIdx.x * blockDim.x + threadIdx.x;
    if (i >= E * CH) return;
    int e = i / CH;
    int c = i % CH;
    int s = src[e];
    int d = dst[e];
    float sc = dinv[s];
    float4 v = *reinterpret_cast<const float4*>(t + (size_t)s * D + c * 4);
    v.x *= sc; v.y *= sc; v.z *= sc; v.w *= sc;
    float* p = acc + (size_t)d * D + c * 4;
    asm volatile("red.global.add.v4.f32 [%0], {%1, %2, %3, %4};"
                 :: "l"(p), "f"(v.x), "f"(v.y), "f"(v.z), "f"(v.w)
                 : "memory");
}

// ------------------------------- tiled GEMM --------------------------------
// C[i][n] = act( sum_k (dinv[i] * A[i][k]) * W[k][n] + bias[n] )
// A is row-major with stride K. Block: 64 rows x N cols, 256 threads.

template <int K, int N, bool RELU>
__global__ void __launch_bounds__(256)
k_gemm(const float* __restrict__ A, const float* __restrict__ dinv,
       const float* __restrict__ W, const float* __restrict__ bias,
       float* __restrict__ C, int M, int ldc) {
    constexpr int BR = 64;
    constexpr int KC = 64;
    constexpr int CT = N / 4;            // col-group threads (32 for N=128, 16 for N=64)
    constexpr int RTH = 256 / CT;        // row-group threads
    constexpr int RPT = BR / RTH;        // rows per thread (8 or 4)

    __shared__ float Xs[BR][KC];
    __shared__ float Ws[KC][N];

    const int tid = threadIdx.x;
    const int row0 = blockIdx.x * BR;
    const int cx = tid % CT;             // owns cols [4*cx, 4*cx+4)
    const int ry = tid / CT;             // owns rows ry*RPT .. ry*RPT+RPT-1

    float4 acc[RPT];
#pragma unroll
    for (int r = 0; r < RPT; r++) acc[r] = make_float4(0.f, 0.f, 0.f, 0.f);

    for (int kc = 0; kc < K; kc += KC) {
        // load X tile (scaled by dinv), coalesced float4
        for (int i = tid; i < BR * (KC / 4); i += 256) {
            int r = i / (KC / 4);
            int c4 = i % (KC / 4);
            int grow = row0 + r;
            float4 v = make_float4(0.f, 0.f, 0.f, 0.f);
            if (grow < M) {
                v = *reinterpret_cast<const float4*>(A + (size_t)grow * K + kc + c4 * 4);
                float s = dinv[grow];
                v.x *= s; v.y *= s; v.z *= s; v.w *= s;
            }
            *reinterpret_cast<float4*>(&Xs[r][c4 * 4]) = v;
        }
        // load W tile
        for (int i = tid; i < KC * (N / 4); i += 256) {
            int k = i / (N / 4);
            int n4 = i % (N / 4);
            *reinterpret_cast<float4*>(&Ws[k][n4 * 4]) =
                *reinterpret_cast<const float4*>(W + (size_t)(kc + k) * N + n4 * 4);
        }
        __syncthreads();

#pragma unroll 8
        for (int k = 0; k < KC; k++) {
            float4 w = *reinterpret_cast<float4*>(&Ws[k][cx * 4]);
#pragma unroll
            for (int r = 0; r < RPT; r++) {
                float a = Xs[ry * RPT + r][k];
                acc[r].x += a * w.x;
                acc[r].y += a * w.y;
                acc[r].z += a * w.z;
                acc[r].w += a * w.w;
            }
        }
        __syncthreads();
    }

    float4 bb = *reinterpret_cast<const float4*>(bias + cx * 4);
#pragma unroll
    for (int r = 0; r < RPT; r++) {
        int grow = row0 + ry * RPT + r;
        if (grow < M) {
            float4 o = acc[r];
            o.x += bb.x; o.y += bb.y; o.z += bb.z; o.w += bb.w;
            if (RELU) {
                o.x = fmaxf(o.x, 0.f); o.y = fmaxf(o.y, 0.f);
                o.z = fmaxf(o.z, 0.f); o.w = fmaxf(o.w, 0.f);
            }
            *reinterpret_cast<float4*>(C + (size_t)grow * ldc + cx * 4) = o;
        }
    }
}

// ------------------------------- launcher ----------------------------------

extern "C" void kernel_launch(void* const* d_in, const int* in_sizes, int n_in,
                              void* d_out, int out_size) {
    const float* x   = (const float*)d_in[0];
    const int*   ei  = (const int*)  d_in[1];
    const float* W1  = (const float*)d_in[2];
    const float* b1  = (const float*)d_in[3];
    const float* W2  = (const float*)d_in[4];
    const float* b2  = (const float*)d_in[5];
    const float* Wmu = (const float*)d_in[6];
    const float* bmu = (const float*)d_in[7];
    const float* Wlv = (const float*)d_in[8];
    const float* blv = (const float*)d_in[9];
    float* out = (float*)d_out;

    const int M = in_sizes[0] / 64;      // 100000
    const int E = in_sizes[1] / 2;       // 1600000
    const int* src = ei;
    const int* dst = ei + E;

    float *deg, *dinv, *bufA, *bufB;
    cudaGetSymbolAddress((void**)&deg,  g_deg);
    cudaGetSymbolAddress((void**)&dinv, g_dinv);
    cudaGetSymbolAddress((void**)&bufA, g_bufA);
    cudaGetSymbolAddress((void**)&bufB, g_bufB);

    const int T = 256;
    auto nb = [](long n, int t) { return (int)((n + t - 1) / t); };

    // degrees (with self loops) -> dinv
    k_init_deg <<<nb(M, T), T>>>(deg, M);
    k_count_deg<<<nb(E, T), T>>>(dst, deg, E);
    k_dinv     <<<nb(M, T), T>>>(deg, dinv, M);

    // ---- layer 1: aggregate x (64) then GEMM 64->128, relu ----
    k_init_acc<64><<<nb((long)M * 16, T), T>>>(bufA, x, dinv, M);
    k_scatter <64><<<nb((long)E * 16, T), T>>>(bufA, x, src, dst, dinv, E);
    k_gemm<64, 128, true><<<nb(M, 64), T>>>(bufA, dinv, W1, b1, bufB, M, 128);

    // ---- layer 2: aggregate h1 (128) then GEMM 128->128, relu ----
    k_init_acc<128><<<nb((long)M * 32, T), T>>>(bufA, bufB, dinv, M);
    k_scatter <128><<<nb((long)E * 32, T), T>>>(bufA, bufB, src, dst, dinv, E);
    k_gemm<128, 128, true><<<nb(M, 64), T>>>(bufA, dinv, W2, b2, bufB, M, 128);

    // ---- heads: aggregate h2 (128) once, then mu / logvar GEMMs ----
    k_init_acc<128><<<nb((long)M * 32, T), T>>>(bufA, bufB, dinv, M);
    k_scatter <128><<<nb((long)E * 32, T), T>>>(bufA, bufB, src, dst, dinv, E);
    k_gemm<128, 64, false><<<nb(M, 64), T>>>(bufA, dinv, Wmu, bmu, out, M, 64);
    k_gemm<128, 64, false><<<nb(M, 64), T>>>(bufA, dinv, Wlv, blv, out + (size_t)M * 64, M, 64);
}

// round 2
// speedup vs baseline: 1.7541x; 1.7541x over previous
#include <cuda_runtime.h>
#include <cstdint>

// ---------------------------------------------------------------------------
// GCN-VAE encoder. Round 2: CSR-gather aggregation (no atomics on features).
//   agg[i] = dinv_i * ( dinv_i * t_i + sum_{j in N(i)} dinv_j * t_j )
//   out    = act(agg @ W + b)            (dinv_i factor applied inside GEMM)
// CSR (by dst) is rebuilt every launch: histogram -> block scan -> atomic fill.
// ---------------------------------------------------------------------------

#define N_NODES 100000
#define E_MAX   1700000
#define MAXD    128

__device__ int   g_cnt   [N_NODES];
__device__ int   g_off   [N_NODES + 1];
__device__ int   g_cursor[N_NODES];
__device__ int   g_bsum  [128];
__device__ int   g_csr   [E_MAX];
__device__ float g_dinv  [N_NODES];
__device__ float g_bufA[(size_t)N_NODES * MAXD];   // aggregated features
__device__ float g_bufB[(size_t)N_NODES * MAXD];   // hidden activations

// ----------------------------- degree / CSR --------------------------------

__global__ void k_zero_cnt(int* __restrict__ cnt, int n) {
    int i = blockIdx.x * blockDim.x + threadIdx.x;
    if (i < n) cnt[i] = 0;
}

__global__ void k_hist(const int* __restrict__ dst, int* __restrict__ cnt, int E) {
    int i = blockIdx.x * blockDim.x + threadIdx.x;
    if (i < E) atomicAdd(&cnt[dst[i]], 1);
}

__global__ void k_dinv(const int* __restrict__ cnt, float* __restrict__ dinv, int n) {
    int i = blockIdx.x * blockDim.x + threadIdx.x;
    if (i < n) dinv[i] = rsqrtf((float)(cnt[i] + 1));   // +1 self loop
}

// --- 3-kernel exclusive scan over cnt (1024 elems / block, 256 threads) ---

__global__ void k_scan1(const int* __restrict__ cnt, int* __restrict__ off,
                        int* __restrict__ bsum, int n) {
    __shared__ int s[256];
    const int tid = threadIdx.x;
    const int base = blockIdx.x * 1024 + tid * 4;
    int v[4], tsum = 0;
#pragma unroll
    for (int r = 0; r < 4; r++) {
        int idx = base + r;
        v[r] = (idx < n) ? cnt[idx] : 0;
        tsum += v[r];
    }
    s[tid] = tsum;
    __syncthreads();
    for (int d = 1; d < 256; d <<= 1) {
        int add = (tid >= d) ? s[tid - d] : 0;
        __syncthreads();
        s[tid] += add;
        __syncthreads();
    }
    int run = s[tid] - tsum;                 // exclusive prefix of this thread
#pragma unroll
    for (int r = 0; r < 4; r++) {
        int idx = base + r;
        if (idx < n) off[idx] = run;
        run += v[r];
    }
    if (tid == 255) bsum[blockIdx.x] = s[255];
}

__global__ void k_scan2(int* __restrict__ bsum, int nb) {
    __shared__ int s[128];
    int tid = threadIdx.x;
    int v = (tid < nb) ? bsum[tid] : 0;
    s[tid] = v;
    __syncthreads();
    for (int d = 1; d < 128; d <<= 1) {
        int add = (tid >= d) ? s[tid - d] : 0;
        __syncthreads();
        s[tid] += add;
        __syncthreads();
    }
    if (tid < nb) bsum[tid] = s[tid] - v;    // exclusive
}

__global__ void k_scan3(int* __restrict__ off, int* __restrict__ cursor,
                        const int* __restrict__ bsum, int n, int E) {
    int i = blockIdx.x * blockDim.x + threadIdx.x;
    if (i < n) {
        int o = off[i] + bsum[i >> 10];
        off[i] = o;
        cursor[i] = o;
    }
    if (i == 0) off[n] = E;
}

__global__ void k_fill(const int* __restrict__ src, const int* __restrict__ dst,
                       int* __restrict__ cursor, int* __restrict__ csr, int E) {
    int i = blockIdx.x * blockDim.x + threadIdx.x;
    if (i < E) {
        int pos = atomicAdd(&cursor[dst[i]], 1);
        csr[pos] = src[i];
    }
}

// ----------------------------- gather SpMM ---------------------------------
// One G-lane group per dst node; each lane owns a float4 column chunk.
// acc = dinv_i * t_i + sum_j dinv_j * t_j (outer dinv_i applied in GEMM).

template <int D>
__global__ void __launch_bounds__(256)
k_gather(float* __restrict__ acc, const float* __restrict__ t,
         const int* __restrict__ csr, const int* __restrict__ off,
         const float* __restrict__ dinv, int n) {
    constexpr int G = D / 4;                       // 16 lanes (D=64) / 32 (D=128)
    int gid  = (blockIdx.x * blockDim.x + threadIdx.x) / G;
    int lane = threadIdx.x % G;
    if (gid >= n) return;

    // self loop
    float w = dinv[gid];
    float4 v = *reinterpret_cast<const float4*>(t + (size_t)gid * D + lane * 4);
    float4 a = make_float4(w * v.x, w * v.y, w * v.z, w * v.w);

    int e   = off[gid];
    int end = off[gid + 1];
    for (; e + 2 <= end; e += 2) {
        int   s0 = csr[e],     s1 = csr[e + 1];
        float w0 = dinv[s0],   w1 = dinv[s1];
        float4 v0 = *reinterpret_cast<const float4*>(t + (size_t)s0 * D + lane * 4);
        float4 v1 = *reinterpret_cast<const float4*>(t + (size_t)s1 * D + lane * 4);
        a.x += w0 * v0.x + w1 * v1.x;
        a.y += w0 * v0.y + w1 * v1.y;
        a.z += w0 * v0.z + w1 * v1.z;
        a.w += w0 * v0.w + w1 * v1.w;
    }
    if (e < end) {
        int s0 = csr[e];
        float w0 = dinv[s0];
        float4 v0 = *reinterpret_cast<const float4*>(t + (size_t)s0 * D + lane * 4);
        a.x += w0 * v0.x; a.y += w0 * v0.y; a.z += w0 * v0.z; a.w += w0 * v0.w;
    }
    *reinterpret_cast<float4*>(acc + (size_t)gid * D + lane * 4) = a;
}

// ------------------------------- tiled GEMM --------------------------------
// C[i][n] = act( sum_k (dinv[i] * A[i][k]) * W[k][n] + bias[n] )

template <int K, int N, bool RELU>
__global__ void __launch_bounds__(256)
k_gemm(const float* __restrict__ A, const float* __restrict__ dinv,
       const float* __restrict__ W, const float* __restrict__ bias,
       float* __restrict__ C, int M, int ldc) {
    constexpr int BR = 64;
    constexpr int KC = 64;
    constexpr int CT = N / 4;
    constexpr int RTH = 256 / CT;
    constexpr int RPT = BR / RTH;

    __shared__ float Xs[BR][KC];
    __shared__ float Ws[KC][N];

    const int tid = threadIdx.x;
    const int row0 = blockIdx.x * BR;
    const int cx = tid % CT;
    const int ry = tid / CT;

    float4 acc[RPT];
#pragma unroll
    for (int r = 0; r < RPT; r++) acc[r] = make_float4(0.f, 0.f, 0.f, 0.f);

    for (int kc = 0; kc < K; kc += KC) {
        for (int i = tid; i < BR * (KC / 4); i += 256) {
            int r = i / (KC / 4);
            int c4 = i % (KC / 4);
            int grow = row0 + r;
            float4 v = make_float4(0.f, 0.f, 0.f, 0.f);
            if (grow < M) {
                v = *reinterpret_cast<const float4*>(A + (size_t)grow * K + kc + c4 * 4);
                float s = dinv[grow];
                v.x *= s; v.y *= s; v.z *= s; v.w *= s;
            }
            *reinterpret_cast<float4*>(&Xs[r][c4 * 4]) = v;
        }
        for (int i = tid; i < KC * (N / 4); i += 256) {
            int k = i / (N / 4);
            int n4 = i % (N / 4);
            *reinterpret_cast<float4*>(&Ws[k][n4 * 4]) =
                *reinterpret_cast<const float4*>(W + (size_t)(kc + k) * N + n4 * 4);
        }
        __syncthreads();

#pragma unroll 8
        for (int k = 0; k < KC; k++) {
            float4 w = *reinterpret_cast<float4*>(&Ws[k][cx * 4]);
#pragma unroll
            for (int r = 0; r < RPT; r++) {
                float a = Xs[ry * RPT + r][k];
                acc[r].x += a * w.x;
                acc[r].y += a * w.y;
                acc[r].z += a * w.z;
                acc[r].w += a * w.w;
            }
        }
        __syncthreads();
    }

    float4 bb = *reinterpret_cast<const float4*>(bias + cx * 4);
#pragma unroll
    for (int r = 0; r < RPT; r++) {
        int grow = row0 + ry * RPT + r;
        if (grow < M) {
            float4 o = acc[r];
            o.x += bb.x; o.y += bb.y; o.z += bb.z; o.w += bb.w;
            if (RELU) {
                o.x = fmaxf(o.x, 0.f); o.y = fmaxf(o.y, 0.f);
                o.z = fmaxf(o.z, 0.f); o.w = fmaxf(o.w, 0.f);
            }
            *reinterpret_cast<float4*>(C + (size_t)grow * ldc + cx * 4) = o;
        }
    }
}

// ------------------------------- launcher ----------------------------------

extern "C" void kernel_launch(void* const* d_in, const int* in_sizes, int n_in,
                              void* d_out, int out_size) {
    const float* x   = (const float*)d_in[0];
    const int*   ei  = (const int*)  d_in[1];
    const float* W1  = (const float*)d_in[2];
    const float* b1  = (const float*)d_in[3];
    const float* W2  = (const float*)d_in[4];
    const float* b2  = (const float*)d_in[5];
    const float* Wmu = (const float*)d_in[6];
    const float* bmu = (const float*)d_in[7];
    const float* Wlv = (const float*)d_in[8];
    const float* blv = (const float*)d_in[9];
    float* out = (float*)d_out;

    const int M = in_sizes[0] / 64;
    const int E = in_sizes[1] / 2;
    const int* src = ei;
    const int* dst = ei + E;

    int *cnt, *off, *cursor, *bsum, *csr;
    float *dinv, *bufA, *bufB;
    cudaGetSymbolAddress((void**)&cnt,    g_cnt);
    cudaGetSymbolAddress((void**)&off,    g_off);
    cudaGetSymbolAddress((void**)&cursor, g_cursor);
    cudaGetSymbolAddress((void**)&bsum,   g_bsum);
    cudaGetSymbolAddress((void**)&csr,    g_csr);
    cudaGetSymbolAddress((void**)&dinv,   g_dinv);
    cudaGetSymbolAddress((void**)&bufA,   g_bufA);
    cudaGetSymbolAddress((void**)&bufB,   g_bufB);

    const int T = 256;
    auto nb = [](long n, int t) { return (int)((n + t - 1) / t); };
    const int nscan = nb(M, 1024);

    // CSR build (by dst) + dinv
    k_zero_cnt<<<nb(M, T), T>>>(cnt, M);
    k_hist    <<<nb(E, T), T>>>(dst, cnt, E);
    k_dinv    <<<nb(M, T), T>>>(cnt, dinv, M);
    k_scan1   <<<nscan, 256>>>(cnt, off, bsum, M);
    k_scan2   <<<1, 128>>>(bsum, nscan);
    k_scan3   <<<nb(M, T), T>>>(off, cursor, bsum, M, E);
    k_fill    <<<nb(E, T), T>>>(src, dst, cursor, csr, E);

    // layer 1: gather x (64) -> GEMM 64->128 relu
    k_gather<64><<<nb((long)M * 16, T), T>>>(bufA, x, csr, off, dinv, M);
    k_gemm<64, 128, true><<<nb(M, 64), T>>>(bufA, dinv, W1, b1, bufB, M, 128);

    // layer 2: gather h1 (128) -> GEMM 128->128 relu
    k_gather<128><<<nb((long)M * 32, T), T>>>(bufA, bufB, csr, off, dinv, M);
    k_gemm<128, 128, true><<<nb(M, 64), T>>>(bufA, dinv, W2, b2, bufB, M, 128);

    // heads: gather h2 (128) once -> mu / logvar GEMMs
    k_gather<128><<<nb((long)M * 32, T), T>>>(bufA, bufB, csr, off, dinv, M);
    k_gemm<128, 64, false><<<nb(M, 64), T>>>(bufA, dinv, Wmu, bmu, out, M, 64);
    k_gemm<128, 64, false><<<nb(M, 64), T>>>(bufA, dinv, Wlv, blv, out + (size_t)M * 64, M, 64);
}

// round 3
// speedup vs baseline: 1.9518x; 1.1127x over previous
#include <cuda_runtime.h>
#include <cstdint>

// ---------------------------------------------------------------------------
// GCN-VAE encoder. Round 3: FFMA2 (fma.rn.f32x2) GEMM + fused mu/logvar heads.
//   agg[i] = dinv_i * ( dinv_i * t_i + sum_{j in N(i)} dinv_j * t_j )
//   out    = act(agg @ W + b)
// CSR (by dst) rebuilt per launch. Gather applies the outer dinv_i scale.
// ---------------------------------------------------------------------------

#define N_NODES 100000
#define E_MAX   1700000
#define MAXD    128

__device__ int   g_cnt   [N_NODES];
__device__ int   g_off   [N_NODES + 1];
__device__ int   g_cursor[N_NODES];
__device__ int   g_bsum  [128];
__device__ int   g_csr   [E_MAX];
__device__ float g_dinv  [N_NODES];
__device__ float g_bufA[(size_t)N_NODES * MAXD];
__device__ float g_bufB[(size_t)N_NODES * MAXD];

// ------------------------------ f32x2 PTX -----------------------------------

#define PACK2(out, lo, hi) \
    asm("mov.b64 %0, {%1, %2};" : "=l"(out) : "f"(lo), "f"(hi))
#define UNPACK2(lo, hi, in) \
    asm("mov.b64 {%0, %1}, %2;" : "=f"(lo), "=f"(hi) : "l"(in))
#define FMA2(acc, a, b) \
    asm("fma.rn.f32x2 %0, %1, %2, %0;" : "+l"(acc) : "l"(a), "l"(b))

// ----------------------------- degree / CSR --------------------------------

__global__ void k_zero_cnt(int* __restrict__ cnt, int n) {
    int i = blockIdx.x * blockDim.x + threadIdx.x;
    if (i < n) cnt[i] = 0;
}

__global__ void k_hist(const int* __restrict__ dst, int* __restrict__ cnt, int E) {
    int i = blockIdx.x * blockDim.x + threadIdx.x;
    if (i < E) atomicAdd(&cnt[dst[i]], 1);
}

__global__ void k_dinv(const int* __restrict__ cnt, float* __restrict__ dinv, int n) {
    int i = blockIdx.x * blockDim.x + threadIdx.x;
    if (i < n) dinv[i] = rsqrtf((float)(cnt[i] + 1));
}

__global__ void k_scan1(const int* __restrict__ cnt, int* __restrict__ off,
                        int* __restrict__ bsum, int n) {
    __shared__ int s[256];
    const int tid = threadIdx.x;
    const int base = blockIdx.x * 1024 + tid * 4;
    int v[4], tsum = 0;
#pragma unroll
    for (int r = 0; r < 4; r++) {
        int idx = base + r;
        v[r] = (idx < n) ? cnt[idx] : 0;
        tsum += v[r];
    }
    s[tid] = tsum;
    __syncthreads();
    for (int d = 1; d < 256; d <<= 1) {
        int add = (tid >= d) ? s[tid - d] : 0;
        __syncthreads();
        s[tid] += add;
        __syncthreads();
    }
    int run = s[tid] - tsum;
#pragma unroll
    for (int r = 0; r < 4; r++) {
        int idx = base + r;
        if (idx < n) off[idx] = run;
        run += v[r];
    }
    if (tid == 255) bsum[blockIdx.x] = s[255];
}

__global__ void k_scan2(int* __restrict__ bsum, int nb) {
    __shared__ int s[128];
    int tid = threadIdx.x;
    int v = (tid < nb) ? bsum[tid] : 0;
    s[tid] = v;
    __syncthreads();
    for (int d = 1; d < 128; d <<= 1) {
        int add = (tid >= d) ? s[tid - d] : 0;
        __syncthreads();
        s[tid] += add;
        __syncthreads();
    }
    if (tid < nb) bsum[tid] = s[tid] - v;
}

__global__ void k_scan3(int* __restrict__ off, int* __restrict__ cursor,
                        const int* __restrict__ bsum, int n, int E) {
    int i = blockIdx.x * blockDim.x + threadIdx.x;
    if (i < n) {
        int o = off[i] + bsum[i >> 10];
        off[i] = o;
        cursor[i] = o;
    }
    if (i == 0) off[n] = E;
}

__global__ void k_fill(const int* __restrict__ src, const int* __restrict__ dst,
                       int* __restrict__ cursor, int* __restrict__ csr, int E) {
    int i = blockIdx.x * blockDim.x + threadIdx.x;
    if (i < E) {
        int pos = atomicAdd(&cursor[dst[i]], 1);
        csr[pos] = src[i];
    }
}

// ----------------------------- gather SpMM ---------------------------------
// acc = dinv_i * ( dinv_i * t_i + sum_j dinv_j * t_j )

template <int D>
__global__ void __launch_bounds__(256)
k_gather(float* __restrict__ acc, const float* __restrict__ t,
         const int* __restrict__ csr, const int* __restrict__ off,
         const float* __restrict__ dinv, int n) {
    constexpr int G = D / 4;
    int gid  = (blockIdx.x * blockDim.x + threadIdx.x) / G;
    int lane = threadIdx.x % G;
    if (gid >= n) return;

    float w = dinv[gid];
    float4 v = *reinterpret_cast<const float4*>(t + (size_t)gid * D + lane * 4);
    float4 a = make_float4(w * v.x, w * v.y, w * v.z, w * v.w);

    int e   = off[gid];
    int end = off[gid + 1];
    for (; e + 4 <= end; e += 4) {
        int s0 = csr[e], s1 = csr[e + 1], s2 = csr[e + 2], s3 = csr[e + 3];
        float w0 = dinv[s0], w1 = dinv[s1], w2 = dinv[s2], w3 = dinv[s3];
        float4 v0 = *reinterpret_cast<const float4*>(t + (size_t)s0 * D + lane * 4);
        float4 v1 = *reinterpret_cast<const float4*>(t + (size_t)s1 * D + lane * 4);
        float4 v2 = *reinterpret_cast<const float4*>(t + (size_t)s2 * D + lane * 4);
        float4 v3 = *reinterpret_cast<const float4*>(t + (size_t)s3 * D + lane * 4);
        a.x += w0 * v0.x + w1 * v1.x + w2 * v2.x + w3 * v3.x;
        a.y += w0 * v0.y + w1 * v1.y + w2 * v2.y + w3 * v3.y;
        a.z += w0 * v0.z + w1 * v1.z + w2 * v2.z + w3 * v3.z;
        a.w += w0 * v0.w + w1 * v1.w + w2 * v2.w + w3 * v3.w;
    }
    for (; e < end; e++) {
        int s0 = csr[e];
        float w0 = dinv[s0];
        float4 v0 = *reinterpret_cast<const float4*>(t + (size_t)s0 * D + lane * 4);
        a.x += w0 * v0.x; a.y += w0 * v0.y; a.z += w0 * v0.z; a.w += w0 * v0.w;
    }
    // outer dinv_i scale applied here so the GEMM is a plain A@W
    a.x *= w; a.y *= w; a.z *= w; a.w *= w;
    *reinterpret_cast<float4*>(acc + (size_t)gid * D + lane * 4) = a;
}

// ------------------------------ FFMA2 GEMM ----------------------------------
// C = act(A @ W + b). Block tile 64 rows x 128 cols, 128 threads, each thread
// owns 8 rows x 8 cols accumulated as f32x2 pairs (fma.rn.f32x2).
// SPLIT: cols [0,64) from W0/b0 -> C0 (ld 64), cols [64,128) from W1/b1 -> C1.

template <int K, bool RELU, bool SPLIT>
__global__ void __launch_bounds__(128)
k_gemm2(const float* __restrict__ A,
        const float* __restrict__ W0, const float* __restrict__ b0,
        const float* __restrict__ W1, const float* __restrict__ b1,
        float* __restrict__ C0, float* __restrict__ C1, int M) {
    constexpr int BR = 64;
    constexpr int KC = 32;
    constexpr int XP = 33;                // Xs row pad (conflict-free)

    __shared__ float Xs[BR][XP];
    __shared__ float Ws[KC][128];

    const int tid = threadIdx.x;
    const int cx = tid & 15;              // 16 col-threads, 8 cols each
    const int ry = tid >> 4;              // 8 row-threads, 8 rows each
    const int row0 = blockIdx.x * BR;

    unsigned long long acc[8][4];
#pragma unroll
    for (int r = 0; r < 8; r++)
#pragma unroll
        for (int p = 0; p < 4; p++) acc[r][p] = 0ull;

    for (int kc = 0; kc < K; kc += KC) {
        // X tile: 64 x 32, scalar STS into padded rows (conflict-free)
#pragma unroll
        for (int i = tid; i < BR * (KC / 4); i += 128) {
            int r = i >> 3;
            int c4 = i & 7;
            int grow = row0 + r;
            float4 v = make_float4(0.f, 0.f, 0.f, 0.f);
            if (grow < M)
                v = *reinterpret_cast<const float4*>(A + (size_t)grow * K + kc + c4 * 4);
            Xs[r][c4 * 4 + 0] = v.x;
            Xs[r][c4 * 4 + 1] = v.y;
            Xs[r][c4 * 4 + 2] = v.z;
            Xs[r][c4 * 4 + 3] = v.w;
        }
        // W tile: 32 x 128
#pragma unroll
        for (int i = tid; i < KC * 32; i += 128) {
            int k = i >> 5;
            int n4 = i & 31;
            float4 v;
            if (!SPLIT) {
                v = *reinterpret_cast<const float4*>(W0 + (size_t)(kc + k) * 128 + n4 * 4);
            } else if (n4 < 16) {
                v = *reinterpret_cast<const float4*>(W0 + (size_t)(kc + k) * 64 + n4 * 4);
            } else {
                v = *reinterpret_cast<const float4*>(W1 + (size_t)(kc + k) * 64 + (n4 - 16) * 4);
            }
            *reinterpret_cast<float4*>(&Ws[k][n4 * 4]) = v;
        }
        __syncthreads();

#pragma unroll 8
        for (int k = 0; k < KC; k++) {
            float4 wa = *reinterpret_cast<float4*>(&Ws[k][cx * 8]);
            float4 wb = *reinterpret_cast<float4*>(&Ws[k][cx * 8 + 4]);
            unsigned long long w0, w1, w2, w3;
            PACK2(w0, wa.x, wa.y);
            PACK2(w1, wa.z, wa.w);
            PACK2(w2, wb.x, wb.y);
            PACK2(w3, wb.z, wb.w);
#pragma unroll
            for (int r = 0; r < 8; r++) {
                float a = Xs[ry * 8 + r][k];
                unsigned long long ap;
                PACK2(ap, a, a);
                FMA2(acc[r][0], ap, w0);
                FMA2(acc[r][1], ap, w1);
                FMA2(acc[r][2], ap, w2);
                FMA2(acc[r][3], ap, w3);
            }
        }
        __syncthreads();
    }

    // epilogue
    float bias[8];
    if (!SPLIT) {
#pragma unroll
        for (int j = 0; j < 8; j++) bias[j] = b0[cx * 8 + j];
    } else if (cx < 8) {
#pragma unroll
        for (int j = 0; j < 8; j++) bias[j] = b0[cx * 8 + j];
    } else {
#pragma unroll
        for (int j = 0; j < 8; j++) bias[j] = b1[(cx - 8) * 8 + j];
    }

#pragma unroll
    for (int r = 0; r < 8; r++) {
        int grow = row0 + ry * 8 + r;
        if (grow >= M) continue;
        float o[8];
#pragma unroll
        for (int p = 0; p < 4; p++) UNPACK2(o[2 * p], o[2 * p + 1], acc[r][p]);
#pragma unroll
        for (int j = 0; j < 8; j++) {
            o[j] += bias[j];
            if (RELU) o[j] = fmaxf(o[j], 0.f);
        }
        float* dstp;
        if (!SPLIT)      dstp = C0 + (size_t)grow * 128 + cx * 8;
        else if (cx < 8) dstp = C0 + (size_t)grow * 64 + cx * 8;
        else             dstp = C1 + (size_t)grow * 64 + (cx - 8) * 8;
        *reinterpret_cast<float4*>(dstp)     = make_float4(o[0], o[1], o[2], o[3]);
        *reinterpret_cast<float4*>(dstp + 4) = make_float4(o[4], o[5], o[6], o[7]);
    }
}

// ------------------------------- launcher ----------------------------------

extern "C" void kernel_launch(void* const* d_in, const int* in_sizes, int n_in,
                              void* d_out, int out_size) {
    const float* x   = (const float*)d_in[0];
    const int*   ei  = (const int*)  d_in[1];
    const float* W1  = (const float*)d_in[2];
    const float* b1  = (const float*)d_in[3];
    const float* W2  = (const float*)d_in[4];
    const float* b2  = (const float*)d_in[5];
    const float* Wmu = (const float*)d_in[6];
    const float* bmu = (const float*)d_in[7];
    const float* Wlv = (const float*)d_in[8];
    const float* blv = (const float*)d_in[9];
    float* out = (float*)d_out;

    const int M = in_sizes[0] / 64;
    const int E = in_sizes[1] / 2;
    const int* src = ei;
    const int* dst = ei + E;

    int *cnt, *off, *cursor, *bsum, *csr;
    float *dinv, *bufA, *bufB;
    cudaGetSymbolAddress((void**)&cnt,    g_cnt);
    cudaGetSymbolAddress((void**)&off,    g_off);
    cudaGetSymbolAddress((void**)&cursor, g_cursor);
    cudaGetSymbolAddress((void**)&bsum,   g_bsum);
    cudaGetSymbolAddress((void**)&csr,    g_csr);
    cudaGetSymbolAddress((void**)&dinv,   g_dinv);
    cudaGetSymbolAddress((void**)&bufA,   g_bufA);
    cudaGetSymbolAddress((void**)&bufB,   g_bufB);

    const int T = 256;
    auto nb = [](long n, int t) { return (int)((n + t - 1) / t); };
    const int nscan = nb(M, 1024);
    const int gB = nb(M, 64);

    // CSR build (by dst) + dinv
    k_zero_cnt<<<nb(M, T), T>>>(cnt, M);
    k_hist    <<<nb(E, T), T>>>(dst, cnt, E);
    k_dinv    <<<nb(M, T), T>>>(cnt, dinv, M);
    k_scan1   <<<nscan, 256>>>(cnt, off, bsum, M);
    k_scan2   <<<1, 128>>>(bsum, nscan);
    k_scan3   <<<nb(M, T), T>>>(off, cursor, bsum, M, E);
    k_fill    <<<nb(E, T), T>>>(src, dst, cursor, csr, E);

    // layer 1: gather x (64) -> GEMM 64->128 relu
    k_gather<64><<<nb((long)M * 16, T), T>>>(bufA, x, csr, off, dinv, M);
    k_gemm2<64, true, false><<<gB, 128>>>(bufA, W1, b1, nullptr, nullptr, bufB, nullptr, M);

    // layer 2: gather h1 (128) -> GEMM 128->128 relu
    k_gather<128><<<nb((long)M * 32, T), T>>>(bufA, bufB, csr, off, dinv, M);
    k_gemm2<128, true, false><<<gB, 128>>>(bufA, W2, b2, nullptr, nullptr, bufB, nullptr, M);

    // heads: gather h2 (128) once -> fused mu|logvar GEMM
    k_gather<128><<<nb((long)M * 32, T), T>>>(bufA, bufB, csr, off, dinv, M);
    k_gemm2<128, false, true><<<gB, 128>>>(bufA, Wmu, bmu, Wlv, blv,
                                           out, out + (size_t)M * 64, M);
}

// round 4
// speedup vs baseline: 2.1089x; 1.0805x over previous
#include <cuda_runtime.h>
#include <cuda_fp16.h>
#include <cstdint>

// ---------------------------------------------------------------------------
// GCN-VAE encoder. Round 4: fp16 feature storage for gather inputs
// (halves the dominant L2 gather traffic), fp32 accumulate + fp32 GEMM.
//   agg[i] = dinv_i * ( dinv_i * t_i + sum_{j in N(i)} dinv_j * t_j )
//   out    = act(agg @ W + b)
// ---------------------------------------------------------------------------

#define N_NODES 100000
#define E_MAX   1700000
#define MAXD    128

__device__ int    g_cnt   [N_NODES];
__device__ int    g_off   [N_NODES + 1];
__device__ int    g_cursor[N_NODES];
__device__ int    g_bsum  [128];
__device__ int    g_csr   [E_MAX];
__device__ float  g_dinv  [N_NODES];
__device__ float  g_bufA[(size_t)N_NODES * MAXD];    // fp32 aggregated features
__device__ __half g_xh  [(size_t)N_NODES * 64];      // fp16 copy of x
__device__ __half g_bufH[(size_t)N_NODES * MAXD];    // fp16 hidden activations

// ------------------------------ f32x2 PTX -----------------------------------

#define PACK2(out, lo, hi) \
    asm("mov.b64 %0, {%1, %2};" : "=l"(out) : "f"(lo), "f"(hi))
#define UNPACK2(lo, hi, in) \
    asm("mov.b64 {%0, %1}, %2;" : "=f"(lo), "=f"(hi) : "l"(in))
#define FMA2(acc, a, b) \
    asm("fma.rn.f32x2 %0, %1, %2, %0;" : "+l"(acc) : "l"(a), "l"(b))

// ----------------------------- degree / CSR --------------------------------

__global__ void k_zero_cnt(int* __restrict__ cnt, int n) {
    int i = blockIdx.x * blockDim.x + threadIdx.x;
    if (i < n) cnt[i] = 0;
}

__global__ void k_hist(const int* __restrict__ dst, int* __restrict__ cnt, int E) {
    int i = blockIdx.x * blockDim.x + threadIdx.x;
    if (i < E) atomicAdd(&cnt[dst[i]], 1);
}

__global__ void k_dinv(const int* __restrict__ cnt, float* __restrict__ dinv, int n) {
    int i = blockIdx.x * blockDim.x + threadIdx.x;
    if (i < n) dinv[i] = rsqrtf((float)(cnt[i] + 1));
}

__global__ void k_scan1(const int* __restrict__ cnt, int* __restrict__ off,
                        int* __restrict__ bsum, int n) {
    __shared__ int s[256];
    const int tid = threadIdx.x;
    const int base = blockIdx.x * 1024 + tid * 4;
    int v[4], tsum = 0;
#pragma unroll
    for (int r = 0; r < 4; r++) {
        int idx = base + r;
        v[r] = (idx < n) ? cnt[idx] : 0;
        tsum += v[r];
    }
    s[tid] = tsum;
    __syncthreads();
    for (int d = 1; d < 256; d <<= 1) {
        int add = (tid >= d) ? s[tid - d] : 0;
        __syncthreads();
        s[tid] += add;
        __syncthreads();
    }
    int run = s[tid] - tsum;
#pragma unroll
    for (int r = 0; r < 4; r++) {
        int idx = base + r;
        if (idx < n) off[idx] = run;
        run += v[r];
    }
    if (tid == 255) bsum[blockIdx.x] = s[255];
}

__global__ void k_scan2(int* __restrict__ bsum, int nb) {
    __shared__ int s[128];
    int tid = threadIdx.x;
    int v = (tid < nb) ? bsum[tid] : 0;
    s[tid] = v;
    __syncthreads();
    for (int d = 1; d < 128; d <<= 1) {
        int add = (tid >= d) ? s[tid - d] : 0;
        __syncthreads();
        s[tid] += add;
        __syncthreads();
    }
    if (tid < nb) bsum[tid] = s[tid] - v;
}

__global__ void k_scan3(int* __restrict__ off, int* __restrict__ cursor,
                        const int* __restrict__ bsum, int n, int E) {
    int i = blockIdx.x * blockDim.x + threadIdx.x;
    if (i < n) {
        int o = off[i] + bsum[i >> 10];
        off[i] = o;
        cursor[i] = o;
    }
    if (i == 0) off[n] = E;
}

__global__ void k_fill(const int* __restrict__ src, const int* __restrict__ dst,
                       int* __restrict__ cursor, int* __restrict__ csr, int E) {
    int i = blockIdx.x * blockDim.x + threadIdx.x;
    if (i < E) {
        int pos = atomicAdd(&cursor[dst[i]], 1);
        csr[pos] = src[i];
    }
}

// --------------------------- fp32 -> fp16 convert ---------------------------

__global__ void k_cvt(const float* __restrict__ in, __half* __restrict__ outp, long n8) {
    long i = (long)blockIdx.x * blockDim.x + threadIdx.x;
    if (i >= n8) return;
    float4 a = reinterpret_cast<const float4*>(in)[2 * i];
    float4 b = reinterpret_cast<const float4*>(in)[2 * i + 1];
    __half2 h[4];
    h[0] = __float22half2_rn(make_float2(a.x, a.y));
    h[1] = __float22half2_rn(make_float2(a.z, a.w));
    h[2] = __float22half2_rn(make_float2(b.x, b.y));
    h[3] = __float22half2_rn(make_float2(b.z, b.w));
    reinterpret_cast<uint4*>(outp)[i] = *reinterpret_cast<uint4*>(h);
}

// ----------------------------- gather SpMM (fp16 in) ------------------------
// acc = dinv_i * ( dinv_i * t_i + sum_j dinv_j * t_j ),  t stored fp16.
// G = D/8 lanes per node; each lane owns 8 contiguous halves (one uint4).

template <int D>
__global__ void __launch_bounds__(256)
k_gather_h(float* __restrict__ acc, const __half* __restrict__ t,
           const int* __restrict__ csr, const int* __restrict__ off,
           const float* __restrict__ dinv, int n) {
    constexpr int G = D / 8;
    int gid  = (blockIdx.x * blockDim.x + threadIdx.x) / G;
    int lane = threadIdx.x % G;
    if (gid >= n) return;

    float a[8];
    float w = dinv[gid];
    {
        uint4 u = *reinterpret_cast<const uint4*>(t + (size_t)gid * D + lane * 8);
        const __half2* h = reinterpret_cast<const __half2*>(&u);
#pragma unroll
        for (int p = 0; p < 4; p++) {
            float2 f = __half22float2(h[p]);
            a[2 * p]     = w * f.x;
            a[2 * p + 1] = w * f.y;
        }
    }

    int e   = off[gid];
    int end = off[gid + 1];
    for (; e + 4 <= end; e += 4) {
        int s0 = csr[e], s1 = csr[e + 1], s2 = csr[e + 2], s3 = csr[e + 3];
        float w0 = dinv[s0], w1 = dinv[s1], w2 = dinv[s2], w3 = dinv[s3];
        uint4 u0 = *reinterpret_cast<const uint4*>(t + (size_t)s0 * D + lane * 8);
        uint4 u1 = *reinterpret_cast<const uint4*>(t + (size_t)s1 * D + lane * 8);
        uint4 u2 = *reinterpret_cast<const uint4*>(t + (size_t)s2 * D + lane * 8);
        uint4 u3 = *reinterpret_cast<const uint4*>(t + (size_t)s3 * D + lane * 8);
        const __half2* h0 = reinterpret_cast<const __half2*>(&u0);
        const __half2* h1 = reinterpret_cast<const __half2*>(&u1);
        const __half2* h2 = reinterpret_cast<const __half2*>(&u2);
        const __half2* h3 = reinterpret_cast<const __half2*>(&u3);
#pragma unroll
        for (int p = 0; p < 4; p++) {
            float2 f0 = __half22float2(h0[p]);
            float2 f1 = __half22float2(h1[p]);
            float2 f2 = __half22float2(h2[p]);
            float2 f3 = __half22float2(h3[p]);
            a[2 * p]     += w0 * f0.x + w1 * f1.x + w2 * f2.x + w3 * f3.x;
            a[2 * p + 1] += w0 * f0.y + w1 * f1.y + w2 * f2.y + w3 * f3.y;
        }
    }
    for (; e < end; e++) {
        int s0 = csr[e];
        float w0 = dinv[s0];
        uint4 u0 = *reinterpret_cast<const uint4*>(t + (size_t)s0 * D + lane * 8);
        const __half2* h0 = reinterpret_cast<const __half2*>(&u0);
#pragma unroll
        for (int p = 0; p < 4; p++) {
            float2 f0 = __half22float2(h0[p]);
            a[2 * p]     += w0 * f0.x;
            a[2 * p + 1] += w0 * f0.y;
        }
    }

#pragma unroll
    for (int j = 0; j < 8; j++) a[j] *= w;   // outer dinv_i
    float* dstp = acc + (size_t)gid * D + lane * 8;
    *reinterpret_cast<float4*>(dstp)     = make_float4(a[0], a[1], a[2], a[3]);
    *reinterpret_cast<float4*>(dstp + 4) = make_float4(a[4], a[5], a[6], a[7]);
}

// ------------------------------ FFMA2 GEMM ----------------------------------
// C = act(A @ W + b). 64x128 block tile, 128 threads, 8x8 per thread (f32x2).
// HALF_OUT: write fp16 to H (ld 128). SPLIT: cols [0,64)->C0, [64,128)->C1 fp32.

template <int K, bool RELU, bool SPLIT, bool HALF_OUT>
__global__ void __launch_bounds__(128)
k_gemm2(const float* __restrict__ A,
        const float* __restrict__ W0, const float* __restrict__ b0,
        const float* __restrict__ W1, const float* __restrict__ b1,
        float* __restrict__ C0, float* __restrict__ C1,
        __half* __restrict__ H, int M) {
    constexpr int BR = 64;
    constexpr int KC = 32;
    constexpr int XP = 33;

    __shared__ float Xs[BR][XP];
    __shared__ float Ws[KC][128];

    const int tid = threadIdx.x;
    const int cx = tid & 15;
    const int ry = tid >> 4;
    const int row0 = blockIdx.x * BR;

    unsigned long long acc[8][4];
#pragma unroll
    for (int r = 0; r < 8; r++)
#pragma unroll
        for (int p = 0; p < 4; p++) acc[r][p] = 0ull;

    for (int kc = 0; kc < K; kc += KC) {
#pragma unroll
        for (int i = tid; i < BR * (KC / 4); i += 128) {
            int r = i >> 3;
            int c4 = i & 7;
            int grow = row0 + r;
            float4 v = make_float4(0.f, 0.f, 0.f, 0.f);
            if (grow < M)
                v = *reinterpret_cast<const float4*>(A + (size_t)grow * K + kc + c4 * 4);
            Xs[r][c4 * 4 + 0] = v.x;
            Xs[r][c4 * 4 + 1] = v.y;
            Xs[r][c4 * 4 + 2] = v.z;
            Xs[r][c4 * 4 + 3] = v.w;
        }
#pragma unroll
        for (int i = tid; i < KC * 32; i += 128) {
            int k = i >> 5;
            int n4 = i & 31;
            float4 v;
            if (!SPLIT) {
                v = *reinterpret_cast<const float4*>(W0 + (size_t)(kc + k) * 128 + n4 * 4);
            } else if (n4 < 16) {
                v = *reinterpret_cast<const float4*>(W0 + (size_t)(kc + k) * 64 + n4 * 4);
            } else {
                v = *reinterpret_cast<const float4*>(W1 + (size_t)(kc + k) * 64 + (n4 - 16) * 4);
            }
            *reinterpret_cast<float4*>(&Ws[k][n4 * 4]) = v;
        }
        __syncthreads();

#pragma unroll 8
        for (int k = 0; k < KC; k++) {
            float4 wa = *reinterpret_cast<float4*>(&Ws[k][cx * 8]);
            float4 wb = *reinterpret_cast<float4*>(&Ws[k][cx * 8 + 4]);
            unsigned long long w0, w1, w2, w3;
            PACK2(w0, wa.x, wa.y);
            PACK2(w1, wa.z, wa.w);
            PACK2(w2, wb.x, wb.y);
            PACK2(w3, wb.z, wb.w);
#pragma unroll
            for (int r = 0; r < 8; r++) {
                float a = Xs[ry * 8 + r][k];
                unsigned long long ap;
                PACK2(ap, a, a);
                FMA2(acc[r][0], ap, w0);
                FMA2(acc[r][1], ap, w1);
                FMA2(acc[r][2], ap, w2);
                FMA2(acc[r][3], ap, w3);
            }
        }
        __syncthreads();
    }

    float bias[8];
    if (!SPLIT) {
#pragma unroll
        for (int j = 0; j < 8; j++) bias[j] = b0[cx * 8 + j];
    } else if (cx < 8) {
#pragma unroll
        for (int j = 0; j < 8; j++) bias[j] = b0[cx * 8 + j];
    } else {
#pragma unroll
        for (int j = 0; j < 8; j++) bias[j] = b1[(cx - 8) * 8 + j];
    }

#pragma unroll
    for (int r = 0; r < 8; r++) {
        int grow = row0 + ry * 8 + r;
        if (grow >= M) continue;
        float o[8];
#pragma unroll
        for (int p = 0; p < 4; p++) UNPACK2(o[2 * p], o[2 * p + 1], acc[r][p]);
#pragma unroll
        for (int j = 0; j < 8; j++) {
            o[j] += bias[j];
            if (RELU) o[j] = fmaxf(o[j], 0.f);
        }
        if (HALF_OUT) {
            __half2 h[4];
#pragma unroll
            for (int p = 0; p < 4; p++)
                h[p] = __float22half2_rn(make_float2(o[2 * p], o[2 * p + 1]));
            *reinterpret_cast<uint4*>(H + (size_t)grow * 128 + cx * 8) =
                *reinterpret_cast<uint4*>(h);
        } else {
            float* dstp;
            if (!SPLIT)      dstp = C0 + (size_t)grow * 128 + cx * 8;
            else if (cx < 8) dstp = C0 + (size_t)grow * 64 + cx * 8;
            else             dstp = C1 + (size_t)grow * 64 + (cx - 8) * 8;
            *reinterpret_cast<float4*>(dstp)     = make_float4(o[0], o[1], o[2], o[3]);
            *reinterpret_cast<float4*>(dstp + 4) = make_float4(o[4], o[5], o[6], o[7]);
        }
    }
}

// ------------------------------- launcher ----------------------------------

extern "C" void kernel_launch(void* const* d_in, const int* in_sizes, int n_in,
                              void* d_out, int out_size) {
    const float* x   = (const float*)d_in[0];
    const int*   ei  = (const int*)  d_in[1];
    const float* W1  = (const float*)d_in[2];
    const float* b1  = (const float*)d_in[3];
    const float* W2  = (const float*)d_in[4];
    const float* b2  = (const float*)d_in[5];
    const float* Wmu = (const float*)d_in[6];
    const float* bmu = (const float*)d_in[7];
    const float* Wlv = (const float*)d_in[8];
    const float* blv = (const float*)d_in[9];
    float* out = (float*)d_out;

    const int M = in_sizes[0] / 64;
    const int E = in_sizes[1] / 2;
    const int* src = ei;
    const int* dst = ei + E;

    int *cnt, *off, *cursor, *bsum, *csr;
    float *dinv, *bufA;
    __half *xh, *bufH;
    cudaGetSymbolAddress((void**)&cnt,    g_cnt);
    cudaGetSymbolAddress((void**)&off,    g_off);
    cudaGetSymbolAddress((void**)&cursor, g_cursor);
    cudaGetSymbolAddress((void**)&bsum,   g_bsum);
    cudaGetSymbolAddress((void**)&csr,    g_csr);
    cudaGetSymbolAddress((void**)&dinv,   g_dinv);
    cudaGetSymbolAddress((void**)&bufA,   g_bufA);
    cudaGetSymbolAddress((void**)&xh,     g_xh);
    cudaGetSymbolAddress((void**)&bufH,   g_bufH);

    const int T = 256;
    auto nb = [](long n, int t) { return (int)((n + t - 1) / t); };
    const int nscan = nb(M, 1024);
    const int gB = nb(M, 64);

    // CSR build (by dst) + dinv + x->fp16
    k_zero_cnt<<<nb(M, T), T>>>(cnt, M);
    k_hist    <<<nb(E, T), T>>>(dst, cnt, E);
    k_dinv    <<<nb(M, T), T>>>(cnt, dinv, M);
    k_scan1   <<<nscan, 256>>>(cnt, off, bsum, M);
    k_scan2   <<<1, 128>>>(bsum, nscan);
    k_scan3   <<<nb(M, T), T>>>(off, cursor, bsum, M, E);
    k_fill    <<<nb(E, T), T>>>(src, dst, cursor, csr, E);
    k_cvt     <<<nb((long)M * 8, T), T>>>(x, xh, (long)M * 8);

    // layer 1: gather xh (64, fp16) -> GEMM 64->128 relu -> fp16 h1
    k_gather_h<64><<<nb((long)M * 8, T), T>>>(bufA, xh, csr, off, dinv, M);
    k_gemm2<64, true, false, true><<<gB, 128>>>(bufA, W1, b1, nullptr, nullptr,
                                                nullptr, nullptr, bufH, M);

    // layer 2: gather h1 (128, fp16) -> GEMM 128->128 relu -> fp16 h2
    k_gather_h<128><<<nb((long)M * 16, T), T>>>(bufA, bufH, csr, off, dinv, M);
    k_gemm2<128, true, false, true><<<gB, 128>>>(bufA, W2, b2, nullptr, nullptr,
                                                 nullptr, nullptr, bufH, M);

    // heads: gather h2 (128, fp16) once -> fused mu|logvar GEMM (fp32 out)
    k_gather_h<128><<<nb((long)M * 16, T), T>>>(bufA, bufH, csr, off, dinv, M);
    k_gemm2<128, false, true, false><<<gB, 128>>>(bufA, Wmu, bmu, Wlv, blv,
                                                  out, out + (size_t)M * 64,
                                                  nullptr, M);
}

// round 5
// speedup vs baseline: 3.1243x; 1.4815x over previous
#include <cuda_runtime.h>
#include <cuda_fp16.h>
#include <cstdint>

// ---------------------------------------------------------------------------
// GCN-VAE encoder. Round 5: HMMA (mma.sync m16n8k16 fp16->fp32) GEMMs.
//   agg fp16 = dinv_i * ( dinv_i * t_i + sum_j dinv_j * t_j ),  fp32 accum
//   out     = act(agg @ W + b),  tensor-core GEMM, fp32 accum
// ---------------------------------------------------------------------------

#define N_NODES 100000
#define E_MAX   1700000

__device__ int    g_cnt   [N_NODES];
__device__ int    g_off   [N_NODES + 1];
__device__ int    g_cursor[N_NODES];
__device__ int    g_bsum  [128];
__device__ int    g_csr   [E_MAX];
__device__ float  g_dinv  [N_NODES];
__device__ __half g_xh  [(size_t)N_NODES * 64];      // fp16 copy of x
__device__ __half g_aggH[(size_t)N_NODES * 128];     // fp16 aggregated features
__device__ __half g_bufH[(size_t)N_NODES * 128];     // fp16 hidden activations
__device__ __half g_wh1 [64  * 128];
__device__ __half g_wh2 [128 * 128];
__device__ __half g_whh [128 * 128];                 // [Wmu | Wlv]

// ----------------------------- degree / CSR --------------------------------

__global__ void k_zero_cnt(int* __restrict__ cnt, int n) {
    int i = blockIdx.x * blockDim.x + threadIdx.x;
    if (i < n) cnt[i] = 0;
}

__global__ void k_hist(const int* __restrict__ dst, int* __restrict__ cnt, int E) {
    int i = blockIdx.x * blockDim.x + threadIdx.x;
    if (i < E) atomicAdd(&cnt[dst[i]], 1);
}

__global__ void k_dinv(const int* __restrict__ cnt, float* __restrict__ dinv, int n) {
    int i = blockIdx.x * blockDim.x + threadIdx.x;
    if (i < n) dinv[i] = rsqrtf((float)(cnt[i] + 1));
}

__global__ void k_scan1(const int* __restrict__ cnt, int* __restrict__ off,
                        int* __restrict__ bsum, int n) {
    __shared__ int s[256];
    const int tid = threadIdx.x;
    const int base = blockIdx.x * 1024 + tid * 4;
    int v[4], tsum = 0;
#pragma unroll
    for (int r = 0; r < 4; r++) {
        int idx = base + r;
        v[r] = (idx < n) ? cnt[idx] : 0;
        tsum += v[r];
    }
    s[tid] = tsum;
    __syncthreads();
    for (int d = 1; d < 256; d <<= 1) {
        int add = (tid >= d) ? s[tid - d] : 0;
        __syncthreads();
        s[tid] += add;
        __syncthreads();
    }
    int run = s[tid] - tsum;
#pragma unroll
    for (int r = 0; r < 4; r++) {
        int idx = base + r;
        if (idx < n) off[idx] = run;
        run += v[r];
    }
    if (tid == 255) bsum[blockIdx.x] = s[255];
}

__global__ void k_scan2(int* __restrict__ bsum, int nb) {
    __shared__ int s[128];
    int tid = threadIdx.x;
    int v = (tid < nb) ? bsum[tid] : 0;
    s[tid] = v;
    __syncthreads();
    for (int d = 1; d < 128; d <<= 1) {
        int add = (tid >= d) ? s[tid - d] : 0;
        __syncthreads();
        s[tid] += add;
        __syncthreads();
    }
    if (tid < nb) bsum[tid] = s[tid] - v;
}

__global__ void k_scan3(int* __restrict__ off, int* __restrict__ cursor,
                        const int* __restrict__ bsum, int n, int E) {
    int i = blockIdx.x * blockDim.x + threadIdx.x;
    if (i < n) {
        int o = off[i] + bsum[i >> 10];
        off[i] = o;
        cursor[i] = o;
    }
    if (i == 0) off[n] = E;
}

__global__ void k_fill(const int* __restrict__ src, const int* __restrict__ dst,
                       int* __restrict__ cursor, int* __restrict__ csr, int E) {
    int i = blockIdx.x * blockDim.x + threadIdx.x;
    if (i < E) {
        int pos = atomicAdd(&cursor[dst[i]], 1);
        csr[pos] = src[i];
    }
}

// ----------------------- fp32 -> fp16 conversions ---------------------------

__global__ void k_cvt(const float* __restrict__ in, __half* __restrict__ outp, long n8) {
    long i = (long)blockIdx.x * blockDim.x + threadIdx.x;
    if (i >= n8) return;
    float4 a = reinterpret_cast<const float4*>(in)[2 * i];
    float4 b = reinterpret_cast<const float4*>(in)[2 * i + 1];
    __half2 h[4];
    h[0] = __float22half2_rn(make_float2(a.x, a.y));
    h[1] = __float22half2_rn(make_float2(a.z, a.w));
    h[2] = __float22half2_rn(make_float2(b.x, b.y));
    h[3] = __float22half2_rn(make_float2(b.z, b.w));
    reinterpret_cast<uint4*>(outp)[i] = *reinterpret_cast<uint4*>(h);
}

__global__ void k_prep_w(const float* __restrict__ W1, const float* __restrict__ W2,
                         const float* __restrict__ Wmu, const float* __restrict__ Wlv,
                         __half* __restrict__ Wh1, __half* __restrict__ Wh2,
                         __half* __restrict__ Whh) {
    int i = blockIdx.x * blockDim.x + threadIdx.x;
    if (i < 64 * 128)  Wh1[i] = __float2half_rn(W1[i]);
    if (i < 128 * 128) Wh2[i] = __float2half_rn(W2[i]);
    if (i < 128 * 128) {
        int k = i >> 7, j = i & 127;
        Whh[i] = __float2half_rn(j < 64 ? Wmu[k * 64 + j] : Wlv[k * 64 + (j - 64)]);
    }
}

// ----------------------------- gather SpMM (fp16 in/out) --------------------
// aggH = fp16( dinv_i * ( dinv_i * t_i + sum_j dinv_j * t_j ) ), fp32 accum.
// G = D/8 lanes per node; each lane owns 8 contiguous halves (one uint4).

template <int D>
__global__ void __launch_bounds__(256)
k_gather_h(__half* __restrict__ acc, const __half* __restrict__ t,
           const int* __restrict__ csr, const int* __restrict__ off,
           const float* __restrict__ dinv, int n) {
    constexpr int G = D / 8;
    int gid  = (blockIdx.x * blockDim.x + threadIdx.x) / G;
    int lane = threadIdx.x % G;
    if (gid >= n) return;

    float a[8];
    float w = dinv[gid];
    {
        uint4 u = *reinterpret_cast<const uint4*>(t + (size_t)gid * D + lane * 8);
        const __half2* h = reinterpret_cast<const __half2*>(&u);
#pragma unroll
        for (int p = 0; p < 4; p++) {
            float2 f = __half22float2(h[p]);
            a[2 * p]     = w * f.x;
            a[2 * p + 1] = w * f.y;
        }
    }

    int e   = off[gid];
    int end = off[gid + 1];
    for (; e + 4 <= end; e += 4) {
        int s0 = csr[e], s1 = csr[e + 1], s2 = csr[e + 2], s3 = csr[e + 3];
        float w0 = dinv[s0], w1 = dinv[s1], w2 = dinv[s2], w3 = dinv[s3];
        uint4 u0 = *reinterpret_cast<const uint4*>(t + (size_t)s0 * D + lane * 8);
        uint4 u1 = *reinterpret_cast<const uint4*>(t + (size_t)s1 * D + lane * 8);
        uint4 u2 = *reinterpret_cast<const uint4*>(t + (size_t)s2 * D + lane * 8);
        uint4 u3 = *reinterpret_cast<const uint4*>(t + (size_t)s3 * D + lane * 8);
        const __half2* h0 = reinterpret_cast<const __half2*>(&u0);
        const __half2* h1 = reinterpret_cast<const __half2*>(&u1);
        const __half2* h2 = reinterpret_cast<const __half2*>(&u2);
        const __half2* h3 = reinterpret_cast<const __half2*>(&u3);
#pragma unroll
        for (int p = 0; p < 4; p++) {
            float2 f0 = __half22float2(h0[p]);
            float2 f1 = __half22float2(h1[p]);
            float2 f2 = __half22float2(h2[p]);
            float2 f3 = __half22float2(h3[p]);
            a[2 * p]     += w0 * f0.x + w1 * f1.x + w2 * f2.x + w3 * f3.x;
            a[2 * p + 1] += w0 * f0.y + w1 * f1.y + w2 * f2.y + w3 * f3.y;
        }
    }
    for (; e < end; e++) {
        int s0 = csr[e];
        float w0 = dinv[s0];
        uint4 u0 = *reinterpret_cast<const uint4*>(t + (size_t)s0 * D + lane * 8);
        const __half2* h0 = reinterpret_cast<const __half2*>(&u0);
#pragma unroll
        for (int p = 0; p < 4; p++) {
            float2 f0 = __half22float2(h0[p]);
            a[2 * p]     += w0 * f0.x;
            a[2 * p + 1] += w0 * f0.y;
        }
    }

    __half2 hv[4];
#pragma unroll
    for (int p = 0; p < 4; p++)
        hv[p] = __float22half2_rn(make_float2(w * a[2 * p], w * a[2 * p + 1]));
    *reinterpret_cast<uint4*>(acc + (size_t)gid * D + lane * 8) =
        *reinterpret_cast<uint4*>(hv);
}

// ------------------------------- HMMA GEMM ----------------------------------
// C = act(A @ W + b), A fp16 [M,K], W fp16 [K,128], fp32 accum.
// Block: 128 rows x 128 cols, 256 threads (8 warps: 4 row-groups x 2 col-groups).
// Warp tile 32x64 via mma.sync.m16n8k16 + ldmatrix. KC=64 smem chunks.
// SPLIT: fp32 out, cols [0,64)->C0, [64,128)->C1 (ld 64). Else fp16 H (ld 128).

template <int K, bool RELU, bool SPLIT>
__global__ void __launch_bounds__(256)
k_hgemm(const __half* __restrict__ A, const __half* __restrict__ Wh,
        const float* __restrict__ b0, const float* __restrict__ b1,
        __half* __restrict__ H, float* __restrict__ C0, float* __restrict__ C1,
        int M) {
    constexpr int KC = 64;
    __shared__ __half Xs[128][72];    // pad 8 halves: conflict-free ldmatrix
    __shared__ __half Ws[64][136];

    const int tid = threadIdx.x;
    const int wid = tid >> 5;
    const int lane = tid & 31;
    const int mg = wid >> 1;          // row group: rows [mg*32, +32)
    const int ng = wid & 1;           // col group: cols [ng*64, +64)
    const int row0 = blockIdx.x * 128;

    float acc[2][8][4];
#pragma unroll
    for (int mt = 0; mt < 2; mt++)
#pragma unroll
        for (int nt = 0; nt < 8; nt++)
#pragma unroll
            for (int q = 0; q < 4; q++) acc[mt][nt][q] = 0.f;

    for (int kc = 0; kc < K; kc += KC) {
        // A tile: 128 x 64 halves
#pragma unroll
        for (int i = tid; i < 128 * 8; i += 256) {
            int r = i >> 3, c8 = i & 7;
            int grow = row0 + r;
            uint4 v = make_uint4(0u, 0u, 0u, 0u);
            if (grow < M)
                v = *reinterpret_cast<const uint4*>(A + (size_t)grow * K + kc + c8 * 8);
            *reinterpret_cast<uint4*>(&Xs[r][c8 * 8]) = v;
        }
        // W tile: 64 x 128 halves
#pragma unroll
        for (int i = tid; i < 64 * 16; i += 256) {
            int k = i >> 4, n8 = i & 15;
            uint4 v = *reinterpret_cast<const uint4*>(Wh + (size_t)(kc + k) * 128 + n8 * 8);
            *reinterpret_cast<uint4*>(&Ws[k][n8 * 8]) = v;
        }
        __syncthreads();

#pragma unroll
        for (int ks = 0; ks < 4; ks++) {
            uint32_t af[2][4];
#pragma unroll
            for (int mt = 0; mt < 2; mt++) {
                int r = mg * 32 + mt * 16 + (lane & 15);
                int c = ks * 16 + (lane >> 4) * 8;
                uint32_t addr = (uint32_t)__cvta_generic_to_shared(&Xs[r][c]);
                asm volatile(
                    "ldmatrix.sync.aligned.m8n8.x4.shared.b16 {%0,%1,%2,%3}, [%4];"
                    : "=r"(af[mt][0]), "=r"(af[mt][1]), "=r"(af[mt][2]), "=r"(af[mt][3])
                    : "r"(addr));
            }
#pragma unroll
            for (int nt = 0; nt < 8; nt++) {
                int k = ks * 16 + (lane & 15);
                int c = ng * 64 + nt * 8;
                uint32_t addr = (uint32_t)__cvta_generic_to_shared(&Ws[k][c]);
                uint32_t bf0, bf1;
                asm volatile(
                    "ldmatrix.sync.aligned.m8n8.x2.trans.shared.b16 {%0,%1}, [%2];"
                    : "=r"(bf0), "=r"(bf1) : "r"(addr));
#pragma unroll
                for (int mt = 0; mt < 2; mt++) {
                    asm volatile(
                        "mma.sync.aligned.m16n8k16.row.col.f32.f16.f16.f32 "
                        "{%0,%1,%2,%3}, {%4,%5,%6,%7}, {%8,%9}, {%0,%1,%2,%3};"
                        : "+f"(acc[mt][nt][0]), "+f"(acc[mt][nt][1]),
                          "+f"(acc[mt][nt][2]), "+f"(acc[mt][nt][3])
                        : "r"(af[mt][0]), "r"(af[mt][1]), "r"(af[mt][2]), "r"(af[mt][3]),
                          "r"(bf0), "r"(bf1));
                }
            }
        }
        __syncthreads();
    }

    // epilogue: d0/d1 -> (row grp, cols c,c+1); d2/d3 -> (row grp+8, same cols)
    const int tig = lane & 3;
    const int grp = lane >> 2;
#pragma unroll
    for (int mt = 0; mt < 2; mt++) {
#pragma unroll
        for (int nt = 0; nt < 8; nt++) {
            int c = ng * 64 + nt * 8 + tig * 2;
#pragma unroll
            for (int hf = 0; hf < 2; hf++) {
                int r = row0 + mg * 32 + mt * 16 + grp + hf * 8;
                if (r >= M) continue;
                float v0 = acc[mt][nt][hf * 2 + 0];
                float v1 = acc[mt][nt][hf * 2 + 1];
                if (!SPLIT) {
                    v0 += b0[c]; v1 += b0[c + 1];
                    if (RELU) { v0 = fmaxf(v0, 0.f); v1 = fmaxf(v1, 0.f); }
                    *reinterpret_cast<__half2*>(H + (size_t)r * 128 + c) =
                        __floats2half2_rn(v0, v1);
                } else if (c < 64) {
                    v0 += b0[c]; v1 += b0[c + 1];
                    *reinterpret_cast<float2*>(C0 + (size_t)r * 64 + c) =
                        make_float2(v0, v1);
                } else {
                    v0 += b1[c - 64]; v1 += b1[c - 63];
                    *reinterpret_cast<float2*>(C1 + (size_t)r * 64 + (c - 64)) =
                        make_float2(v0, v1);
                }
            }
        }
    }
}

// ------------------------------- launcher ----------------------------------

extern "C" void kernel_launch(void* const* d_in, const int* in_sizes, int n_in,
                              void* d_out, int out_size) {
    const float* x   = (const float*)d_in[0];
    const int*   ei  = (const int*)  d_in[1];
    const float* W1  = (const float*)d_in[2];
    const float* b1  = (const float*)d_in[3];
    const float* W2  = (const float*)d_in[4];
    const float* b2  = (const float*)d_in[5];
    const float* Wmu = (const float*)d_in[6];
    const float* bmu = (const float*)d_in[7];
    const float* Wlv = (const float*)d_in[8];
    const float* blv = (const float*)d_in[9];
    float* out = (float*)d_out;

    const int M = in_sizes[0] / 64;
    const int E = in_sizes[1] / 2;
    const int* src = ei;
    const int* dst = ei + E;

    int *cnt, *off, *cursor, *bsum, *csr;
    float *dinv;
    __half *xh, *aggH, *bufH, *wh1, *wh2, *whh;
    cudaGetSymbolAddress((void**)&cnt,    g_cnt);
    cudaGetSymbolAddress((void**)&off,    g_off);
    cudaGetSymbolAddress((void**)&cursor, g_cursor);
    cudaGetSymbolAddress((void**)&bsum,   g_bsum);
    cudaGetSymbolAddress((void**)&csr,    g_csr);
    cudaGetSymbolAddress((void**)&dinv,   g_dinv);
    cudaGetSymbolAddress((void**)&xh,     g_xh);
    cudaGetSymbolAddress((void**)&aggH,   g_aggH);
    cudaGetSymbolAddress((void**)&bufH,   g_bufH);
    cudaGetSymbolAddress((void**)&wh1,    g_wh1);
    cudaGetSymbolAddress((void**)&wh2,    g_wh2);
    cudaGetSymbolAddress((void**)&whh,    g_whh);

    const int T = 256;
    auto nb = [](long n, int t) { return (int)((n + t - 1) / t); };
    const int nscan = nb(M, 1024);
    const int gB = nb(M, 128);

    // CSR build (by dst) + dinv + weight/x fp16 prep
    k_zero_cnt<<<nb(M, T), T>>>(cnt, M);
    k_hist    <<<nb(E, T), T>>>(dst, cnt, E);
    k_dinv    <<<nb(M, T), T>>>(cnt, dinv, M);
    k_scan1   <<<nscan, 256>>>(cnt, off, bsum, M);
    k_scan2   <<<1, 128>>>(bsum, nscan);
    k_scan3   <<<nb(M, T), T>>>(off, cursor, bsum, M, E);
    k_fill    <<<nb(E, T), T>>>(src, dst, cursor, csr, E);
    k_cvt     <<<nb((long)M * 8, T), T>>>(x, xh, (long)M * 8);
    k_prep_w  <<<64, 256>>>(W1, W2, Wmu, Wlv, wh1, wh2, whh);

    // layer 1: gather xh (64) -> HMMA 64->128 relu -> fp16 h1
    k_gather_h<64><<<nb((long)M * 8, T), T>>>(aggH, xh, csr, off, dinv, M);
    k_hgemm<64, true, false><<<gB, 256>>>(aggH, wh1, b1, nullptr, bufH,
                                          nullptr, nullptr, M);

    // layer 2: gather h1 (128) -> HMMA 128->128 relu -> fp16 h2
    k_gather_h<128><<<nb((long)M * 16, T), T>>>(aggH, bufH, csr, off, dinv, M);
    k_hgemm<128, true, false><<<gB, 256>>>(aggH, wh2, b2, nullptr, bufH,
                                           nullptr, nullptr, M);

    // heads: gather h2 (128) once -> fused mu|logvar HMMA (fp32 split out)
    k_gather_h<128><<<nb((long)M * 16, T), T>>>(aggH, bufH, csr, off, dinv, M);
    k_hgemm<128, false, true><<<gB, 256>>>(aggH, whh, bmu, blv, nullptr,
                                           out, out + (size_t)M * 64, M);
}